// round 10
// baseline (speedup 1.0000x reference)
#include <cuda_runtime.h>
#include <cstdint>
#include <cstddef>

constexpr int H = 4096, B = 32, G4 = 16384;      // hidden, batch, 4H
constexpr int BH = B * H;                        // 131072
constexpr int LAYER_W = G4 * H;                  // weight elems per layer-matrix
constexpr int KSTEPS = H / 16;                   // 256 k16 steps per matrix
constexpr int CH = 8;                            // ksteps per smem chunk
constexpr int NCH = KSTEPS / CH;                 // 32 chunks

// ---------------- scratch (device globals; no allocation) ----------------
__device__ float g_gates[(size_t)G4 * B];        // 2 MB
__device__ uint4 g_xfrag[KSTEPS * B * 4];        // input-act frags  (512 KB)
__device__ uint4 g_hfrag[KSTEPS * B * 4];        // hidden-act frags (512 KB)
__device__ float g_hnew[BH];                     // layer-0 h_new (fp32)

// ---------------- helpers ----------------
__device__ __forceinline__ uint32_t smem_u32(const void* p) {
    uint32_t r;
    asm("{ .reg .u64 t; cvta.to.shared.u64 t, %1; cvt.u32.u64 %0, t; }" : "=r"(r) : "l"(p));
    return r;
}

// split float2 -> (hi bf16x2 = truncation, lo bf16x2 = rn(residual))
__device__ __forceinline__ void split2(float2 p, uint32_t& h, uint32_t& l) {
    uint32_t u0 = __float_as_uint(p.x), u1 = __float_as_uint(p.y);
    h = __byte_perm(u0, u1, 0x7632);                       // {hi16(u0), hi16(u1)}
    float l0 = p.x - __uint_as_float(u0 & 0xFFFF0000u);
    float l1 = p.y - __uint_as_float(u1 & 0xFFFF0000u);
    asm("cvt.rn.bf16x2.f32 %0, %1, %2;" : "=r"(l) : "f"(l1), "f"(l0));  // low=l0
}

__device__ __forceinline__ void mma16816(float* d, const uint32_t* a, uint32_t b0, uint32_t b1) {
    asm volatile(
        "mma.sync.aligned.m16n8k16.row.col.f32.bf16.bf16.f32 "
        "{%0,%1,%2,%3}, {%4,%5,%6,%7}, {%8,%9}, {%0,%1,%2,%3};\n"
        : "+f"(d[0]), "+f"(d[1]), "+f"(d[2]), "+f"(d[3])
        : "r"(a[0]), "r"(a[1]), "r"(a[2]), "r"(a[3]), "r"(b0), "r"(b1));
}

#define CP_ASYNC16(smaddr, gptr) \
    asm volatile("cp.async.cg.shared.global [%0], [%1], 16;" :: "r"(smaddr), "l"(gptr) : "memory")
#define CP_COMMIT()  asm volatile("cp.async.commit_group;" ::: "memory")
#define CP_WAIT1()   asm volatile("cp.async.wait_group 1;" ::: "memory")
#define CP_WAIT0()   asm volatile("cp.async.wait_group 0;" ::: "memory")

// ---------------- prep: fp32 activations -> frag-ordered bf16 hi/lo ----------------
// frag element (c, n, t4): bh0 = bf16x2 of act[n][16c+2t4 .. +1], bh1 = +8 offset; bl* residuals.
__global__ void prep_kernel(const float* __restrict__ x, const float* __restrict__ h) {
    int idx = blockIdx.x * blockDim.x + threadIdx.x;        // 0..65535
    int i2 = idx & 32767;
    const float* s = (idx < 32768) ? x : h;
    uint4* d = (idx < 32768) ? g_xfrag : g_hfrag;
    int t4 = i2 & 3, n = (i2 >> 2) & 31, c = i2 >> 7;
    int k0 = c * 16 + 2 * t4;
    float2 p0 = *(const float2*)&s[(size_t)n * H + k0];
    float2 p1 = *(const float2*)&s[(size_t)n * H + k0 + 8];
    uint4 v;
    split2(p0, v.x, v.z);
    split2(p1, v.y, v.w);
    d[i2] = v;
}

// ---------------- GEMM: gates = Wih@x^T + Whh@h^T + bih + bhh ----------------
__global__ void __launch_bounds__(128, 3) gemm_kernel(
    const float* __restrict__ Wih, const float* __restrict__ Whh,
    const float* __restrict__ bih, const float* __restrict__ bhh)
{
    __shared__ uint4 sB[2][CH][32][4];                       // 32 KB, double-buffered B frags
    const int tid = threadIdx.x, lane = tid & 31, wid = tid >> 5;
    const int g = lane >> 2, t4 = lane & 3;
    const int m0 = blockIdx.x * 64 + wid * 16;               // warp's 16 rows
    const uint32_t sb0 = smem_u32(&sB[0][0][0][0]);

    float acc[4][4] = {};                                    // 4 n-tiles x 4 f32

    #pragma unroll 1
    for (int pass = 0; pass < 2; ++pass) {
        const float* W = pass ? Whh : Wih;
        const uint4* F = pass ? g_hfrag : g_xfrag;
        const size_t Fg = __cvta_generic_to_global((void*)F) ? 0 : 0;  // (silence unused) 
        (void)Fg;

        // stage chunk c into buffer (c&1): 1024 uint4, 8 per thread
        auto stage = [&](int c) {
            uint32_t sd = sb0 + (uint32_t)(c & 1) * 16384u;
            const uint4* gp = F + (size_t)c * 1024 + tid;
            #pragma unroll
            for (int r = 0; r < 8; ++r) {
                const void* gg = (const void*)__cvta_generic_to_global((void*)(gp + r * 128));
                CP_ASYNC16(sd + (uint32_t)(tid + r * 128) * 16u, gg);
            }
            CP_COMMIT();
        };

        stage(0);
        stage(1);
        #pragma unroll 1
        for (int ch = 0; ch < NCH; ++ch) {
            if (ch + 1 < NCH) { CP_WAIT1(); } else { CP_WAIT0(); }
            __syncthreads();
            const int buf = ch & 1;

            // A raw for kstep 0 of this chunk
            int k = (ch * CH) * 16 + 2 * t4;
            const float* p0 = W + (size_t)(m0 + g) * H + k;
            const float* p1 = W + (size_t)(m0 + g + 8) * H + k;
            float2 cur0 = *(const float2*)p0,       cur1 = *(const float2*)p1;
            float2 cur2 = *(const float2*)(p0 + 8), cur3 = *(const float2*)(p1 + 8);

            #pragma unroll
            for (int kk = 0; kk < CH; ++kk) {
                float2 n0, n1, n2, n3;
                if (kk + 1 < CH) {                            // prefetch next kstep's A
                    const float* q0 = p0 + (kk + 1) * 16;
                    const float* q1 = p1 + (kk + 1) * 16;
                    n0 = *(const float2*)q0;       n1 = *(const float2*)q1;
                    n2 = *(const float2*)(q0 + 8); n3 = *(const float2*)(q1 + 8);
                }
                uint32_t ah[4], al[4];
                split2(cur0, ah[0], al[0]);
                split2(cur1, ah[1], al[1]);
                split2(cur2, ah[2], al[2]);
                split2(cur3, ah[3], al[3]);
                #pragma unroll
                for (int t = 0; t < 4; ++t) {
                    uint4 bb = sB[buf][kk][8 * t + g][t4];    // {bh0,bh1,bl0,bl1}
                    mma16816(acc[t], ah, bb.x, bb.y);         // Ah*Bh
                    mma16816(acc[t], ah, bb.z, bb.w);         // Ah*Bl
                    mma16816(acc[t], al, bb.x, bb.y);         // Al*Bh
                }
                if (kk + 1 < CH) { cur0 = n0; cur1 = n1; cur2 = n2; cur3 = n3; }
            }
            __syncthreads();
            if (ch + 2 < NCH) stage(ch + 2);
        }
    }

    // epilogue: add biases, write gates[j][b] (j-major, batch contiguous)
    const int j0 = m0 + g;
    const float bi0 = bih[j0] + bhh[j0];
    const float bi1 = bih[j0 + 8] + bhh[j0 + 8];
    #pragma unroll
    for (int t = 0; t < 4; ++t) {
        int col = 8 * t + 2 * t4;
        *(float2*)&g_gates[(size_t)j0 * B + col] =
            make_float2(acc[t][0] + bi0, acc[t][1] + bi0);
        *(float2*)&g_gates[(size_t)(j0 + 8) * B + col] =
            make_float2(acc[t][2] + bi1, acc[t][3] + bi1);
    }
}

// ---------------- LSTM cell (elementwise) ----------------
__global__ void cell_kernel(const float* __restrict__ prev_c, float* __restrict__ out, int l) {
    int idx = blockIdx.x * blockDim.x + threadIdx.x;         // b*H + h
    int h = idx & (H - 1), b = idx >> 12;
    float gi = g_gates[(size_t)h * B + b];
    float gf = g_gates[(size_t)(H + h) * B + b];
    float gg = g_gates[(size_t)(2 * H + h) * B + b];
    float go = g_gates[(size_t)(3 * H + h) * B + b];
    float si = 1.f / (1.f + expf(-gi));
    float sf = 1.f / (1.f + expf(-gf));
    float so = 1.f / (1.f + expf(-go));
    float c = prev_c[(size_t)l * BH + idx];
    float cn = sf * c + si * tanhf(gg);
    float hn = so * tanhf(cn);
    out[(size_t)(0 * 2 + l) * BH + idx] = hn;                // next_h
    out[(size_t)(1 * 2 + l) * BH + idx] = cn;                // next_c
    if (l == 0) g_hnew[idx] = hn;                            // feeds layer 1
}

// ---------------- launch ----------------
extern "C" void kernel_launch(void* const* d_in, const int* in_sizes, int n_in,
                              void* d_out, int out_size) {
    const float* inputs = (const float*)d_in[0];
    const float* prev_h = (const float*)d_in[1];
    const float* prev_c = (const float*)d_in[2];
    const float* W_ih   = (const float*)d_in[3];
    const float* W_hh   = (const float*)d_in[4];
    const float* b_ih   = (const float*)d_in[5];
    const float* b_hh   = (const float*)d_in[6];
    float* out = (float*)d_out;

    float* hnew_ptr = nullptr;
    cudaGetSymbolAddress((void**)&hnew_ptr, g_hnew);

    // layer 0
    prep_kernel<<<256, 256>>>(inputs, prev_h);
    gemm_kernel<<<256, 128>>>(W_ih, W_hh, b_ih, b_hh);
    cell_kernel<<<512, 256>>>(prev_c, out, 0);
    // layer 1
    prep_kernel<<<256, 256>>>(hnew_ptr, prev_h + (size_t)BH);
    gemm_kernel<<<256, 128>>>(W_ih + (size_t)LAYER_W, W_hh + (size_t)LAYER_W,
                              b_ih + (size_t)G4, b_hh + (size_t)G4);
    cell_kernel<<<512, 256>>>(prev_c, out, 1);
}

// round 11
// speedup vs baseline: 1.0006x; 1.0006x over previous
#include <cuda_runtime.h>
#include <cstdint>
#include <cstddef>

constexpr int H = 4096, B = 32, G4 = 16384;      // hidden, batch, 4H
constexpr int BH = B * H;                        // 131072
constexpr int LAYER_W = G4 * H;                  // weight elems per layer-matrix
constexpr int KSTEPS = H / 16;                   // 256 k16 steps per matrix
constexpr int CH = 8;                            // ksteps per smem chunk
constexpr int NCH = KSTEPS / CH;                 // 32 chunks

// ---------------- scratch (device globals; no allocation) ----------------
__device__ float g_gates[(size_t)G4 * B];        // 2 MB
__device__ uint4 g_xfrag[KSTEPS * B * 4];        // input-act frags  (512 KB)
__device__ uint4 g_hfrag[KSTEPS * B * 4];        // hidden-act frags (512 KB)
__device__ float g_hnew[BH];                     // layer-0 h_new (fp32)

// ---------------- helpers ----------------
__device__ __forceinline__ uint32_t smem_u32(const void* p) {
    uint32_t r;
    asm("{ .reg .u64 t; cvta.to.shared.u64 t, %1; cvt.u32.u64 %0, t; }" : "=r"(r) : "l"(p));
    return r;
}

// split float2 -> (hi bf16x2 = truncation, lo bf16x2 = rn(residual))
__device__ __forceinline__ void split2(float2 p, uint32_t& h, uint32_t& l) {
    uint32_t u0 = __float_as_uint(p.x), u1 = __float_as_uint(p.y);
    h = __byte_perm(u0, u1, 0x7632);                       // {hi16(u0), hi16(u1)}
    float l0 = p.x - __uint_as_float(u0 & 0xFFFF0000u);
    float l1 = p.y - __uint_as_float(u1 & 0xFFFF0000u);
    asm("cvt.rn.bf16x2.f32 %0, %1, %2;" : "=r"(l) : "f"(l1), "f"(l0));  // low=l0
}

__device__ __forceinline__ void mma16816(float* d, const uint32_t* a, uint32_t b0, uint32_t b1) {
    asm volatile(
        "mma.sync.aligned.m16n8k16.row.col.f32.bf16.bf16.f32 "
        "{%0,%1,%2,%3}, {%4,%5,%6,%7}, {%8,%9}, {%0,%1,%2,%3};\n"
        : "+f"(d[0]), "+f"(d[1]), "+f"(d[2]), "+f"(d[3])
        : "r"(a[0]), "r"(a[1]), "r"(a[2]), "r"(a[3]), "r"(b0), "r"(b1));
}

#define CP_ASYNC16(smaddr, gptr) \
    asm volatile("cp.async.cg.shared.global [%0], [%1], 16;" :: "r"(smaddr), "l"(gptr) : "memory")
#define CP_COMMIT()  asm volatile("cp.async.commit_group;" ::: "memory")
#define CP_WAIT1()   asm volatile("cp.async.wait_group 1;" ::: "memory")
#define CP_WAIT0()   asm volatile("cp.async.wait_group 0;" ::: "memory")

// ---------------- prep: fp32 activations -> frag-ordered bf16 hi/lo ----------------
// frag element (c, n, t4): bh0 = bf16x2 of act[n][16c+2t4 .. +1], bh1 = +8 offset; bl* residuals.
__global__ void prep_kernel(const float* __restrict__ x, const float* __restrict__ h) {
    int idx = blockIdx.x * blockDim.x + threadIdx.x;        // 0..65535
    int i2 = idx & 32767;
    const float* s = (idx < 32768) ? x : h;
    uint4* d = (idx < 32768) ? g_xfrag : g_hfrag;
    int t4 = i2 & 3, n = (i2 >> 2) & 31, c = i2 >> 7;
    int k0 = c * 16 + 2 * t4;
    float2 p0 = *(const float2*)&s[(size_t)n * H + k0];
    float2 p1 = *(const float2*)&s[(size_t)n * H + k0 + 8];
    uint4 v;
    split2(p0, v.x, v.z);
    split2(p1, v.y, v.w);
    d[i2] = v;
}

// ---------------- GEMM: gates = Wih@x^T + Whh@h^T + bih + bhh ----------------
__global__ void __launch_bounds__(128, 3) gemm_kernel(
    const float* __restrict__ Wih, const float* __restrict__ Whh,
    const float* __restrict__ bih, const float* __restrict__ bhh)
{
    __shared__ uint4 sB[2][CH][32][4];                       // 32 KB, double-buffered B frags
    const int tid = threadIdx.x, lane = tid & 31, wid = tid >> 5;
    const int g = lane >> 2, t4 = lane & 3;
    const int m0 = blockIdx.x * 64 + wid * 16;               // warp's 16 rows
    const uint32_t sb0 = smem_u32(&sB[0][0][0][0]);

    float acc[4][4] = {};                                    // 4 n-tiles x 4 f32

    #pragma unroll 1
    for (int pass = 0; pass < 2; ++pass) {
        const float* W = pass ? Whh : Wih;
        const uint4* F = pass ? g_hfrag : g_xfrag;
        const size_t Fg = __cvta_generic_to_global((void*)F) ? 0 : 0;  // (silence unused) 
        (void)Fg;

        // stage chunk c into buffer (c&1): 1024 uint4, 8 per thread
        auto stage = [&](int c) {
            uint32_t sd = sb0 + (uint32_t)(c & 1) * 16384u;
            const uint4* gp = F + (size_t)c * 1024 + tid;
            #pragma unroll
            for (int r = 0; r < 8; ++r) {
                const void* gg = (const void*)__cvta_generic_to_global((void*)(gp + r * 128));
                CP_ASYNC16(sd + (uint32_t)(tid + r * 128) * 16u, gg);
            }
            CP_COMMIT();
        };

        stage(0);
        stage(1);
        #pragma unroll 1
        for (int ch = 0; ch < NCH; ++ch) {
            if (ch + 1 < NCH) { CP_WAIT1(); } else { CP_WAIT0(); }
            __syncthreads();
            const int buf = ch & 1;

            // A raw for kstep 0 of this chunk
            int k = (ch * CH) * 16 + 2 * t4;
            const float* p0 = W + (size_t)(m0 + g) * H + k;
            const float* p1 = W + (size_t)(m0 + g + 8) * H + k;
            float2 cur0 = *(const float2*)p0,       cur1 = *(const float2*)p1;
            float2 cur2 = *(const float2*)(p0 + 8), cur3 = *(const float2*)(p1 + 8);

            #pragma unroll
            for (int kk = 0; kk < CH; ++kk) {
                float2 n0, n1, n2, n3;
                if (kk + 1 < CH) {                            // prefetch next kstep's A
                    const float* q0 = p0 + (kk + 1) * 16;
                    const float* q1 = p1 + (kk + 1) * 16;
                    n0 = *(const float2*)q0;       n1 = *(const float2*)q1;
                    n2 = *(const float2*)(q0 + 8); n3 = *(const float2*)(q1 + 8);
                }
                uint32_t ah[4], al[4];
                split2(cur0, ah[0], al[0]);
                split2(cur1, ah[1], al[1]);
                split2(cur2, ah[2], al[2]);
                split2(cur3, ah[3], al[3]);
                #pragma unroll
                for (int t = 0; t < 4; ++t) {
                    uint4 bb = sB[buf][kk][8 * t + g][t4];    // {bh0,bh1,bl0,bl1}
                    mma16816(acc[t], ah, bb.x, bb.y);         // Ah*Bh
                    mma16816(acc[t], ah, bb.z, bb.w);         // Ah*Bl
                    mma16816(acc[t], al, bb.x, bb.y);         // Al*Bh
                }
                if (kk + 1 < CH) { cur0 = n0; cur1 = n1; cur2 = n2; cur3 = n3; }
            }
            __syncthreads();
            if (ch + 2 < NCH) stage(ch + 2);
        }
    }

    // epilogue: add biases, write gates[j][b] (j-major, batch contiguous)
    const int j0 = m0 + g;
    const float bi0 = bih[j0] + bhh[j0];
    const float bi1 = bih[j0 + 8] + bhh[j0 + 8];
    #pragma unroll
    for (int t = 0; t < 4; ++t) {
        int col = 8 * t + 2 * t4;
        *(float2*)&g_gates[(size_t)j0 * B + col] =
            make_float2(acc[t][0] + bi0, acc[t][1] + bi0);
        *(float2*)&g_gates[(size_t)(j0 + 8) * B + col] =
            make_float2(acc[t][2] + bi1, acc[t][3] + bi1);
    }
}

// ---------------- LSTM cell (elementwise) ----------------
__global__ void cell_kernel(const float* __restrict__ prev_c, float* __restrict__ out, int l) {
    int idx = blockIdx.x * blockDim.x + threadIdx.x;         // b*H + h
    int h = idx & (H - 1), b = idx >> 12;
    float gi = g_gates[(size_t)h * B + b];
    float gf = g_gates[(size_t)(H + h) * B + b];
    float gg = g_gates[(size_t)(2 * H + h) * B + b];
    float go = g_gates[(size_t)(3 * H + h) * B + b];
    float si = 1.f / (1.f + expf(-gi));
    float sf = 1.f / (1.f + expf(-gf));
    float so = 1.f / (1.f + expf(-go));
    float c = prev_c[(size_t)l * BH + idx];
    float cn = sf * c + si * tanhf(gg);
    float hn = so * tanhf(cn);
    out[(size_t)(0 * 2 + l) * BH + idx] = hn;                // next_h
    out[(size_t)(1 * 2 + l) * BH + idx] = cn;                // next_c
    if (l == 0) g_hnew[idx] = hn;                            // feeds layer 1
}

// ---------------- launch ----------------
extern "C" void kernel_launch(void* const* d_in, const int* in_sizes, int n_in,
                              void* d_out, int out_size) {
    const float* inputs = (const float*)d_in[0];
    const float* prev_h = (const float*)d_in[1];
    const float* prev_c = (const float*)d_in[2];
    const float* W_ih   = (const float*)d_in[3];
    const float* W_hh   = (const float*)d_in[4];
    const float* b_ih   = (const float*)d_in[5];
    const float* b_hh   = (const float*)d_in[6];
    float* out = (float*)d_out;

    float* hnew_ptr = nullptr;
    cudaGetSymbolAddress((void**)&hnew_ptr, g_hnew);

    // layer 0
    prep_kernel<<<256, 256>>>(inputs, prev_h);
    gemm_kernel<<<256, 128>>>(W_ih, W_hh, b_ih, b_hh);
    cell_kernel<<<512, 256>>>(prev_c, out, 0);
    // layer 1
    prep_kernel<<<256, 256>>>(hnew_ptr, prev_h + (size_t)BH);
    gemm_kernel<<<256, 128>>>(W_ih + (size_t)LAYER_W, W_hh + (size_t)LAYER_W,
                              b_ih + (size_t)G4, b_hh + (size_t)G4);
    cell_kernel<<<512, 256>>>(prev_c, out, 1);
}

// round 12
// speedup vs baseline: 1.1679x; 1.1672x over previous
#include <cuda_runtime.h>
#include <cstdint>
#include <cstddef>

constexpr int H = 4096, B = 32, G4 = 16384;      // hidden, batch, 4H
constexpr int BH = B * H;                        // 131072
constexpr int LAYER_W = G4 * H;                  // weight elems per layer-matrix
constexpr int KSTEPS = H / 16;                   // 256 k16 steps per matrix
constexpr int CH = 8;                            // ksteps per smem chunk (128 floats of K)
constexpr int NCHP = KSTEPS / CH;                // 32 chunks per pass
constexpr int NCH = 2 * NCHP;                    // 64 chunks total (ih pass + hh pass)

// ---- smem layout (bytes, per stage) ----
constexpr int A_STRIDE_F = 132;                  // 128 + 4 pad floats
constexpr int A_STRIDE_B = A_STRIDE_F * 4;       // 528
constexpr int A_BYTES = 128 * A_STRIDE_B;        // 67584
constexpr int B_OFF   = A_BYTES;
constexpr int B_BYTES = CH * 32 * 4 * 16;        // 16384
constexpr int STAGE   = A_BYTES + B_BYTES;       // 83968
constexpr int SMEM_TOTAL = 2 * STAGE;            // 167936

// ---------------- scratch (device globals; no allocation) ----------------
__device__ float g_gates[(size_t)G4 * B];        // 2 MB
__device__ uint4 g_xfrag[KSTEPS * B * 4];        // input-act frags  (512 KB)
__device__ uint4 g_hfrag[KSTEPS * B * 4];        // hidden-act frags (512 KB)
__device__ float g_hnew[BH];                     // layer-0 h_new (fp32)

// ---------------- helpers ----------------
__device__ __forceinline__ uint32_t smem_u32(const void* p) {
    uint32_t r;
    asm("{ .reg .u64 t; cvta.to.shared.u64 t, %1; cvt.u32.u64 %0, t; }" : "=r"(r) : "l"(p));
    return r;
}

// split float2 -> (hi bf16x2 = truncation, lo bf16x2 = rn(residual))
__device__ __forceinline__ void split2(float2 p, uint32_t& h, uint32_t& l) {
    uint32_t u0 = __float_as_uint(p.x), u1 = __float_as_uint(p.y);
    h = __byte_perm(u0, u1, 0x7632);
    float l0 = p.x - __uint_as_float(u0 & 0xFFFF0000u);
    float l1 = p.y - __uint_as_float(u1 & 0xFFFF0000u);
    asm("cvt.rn.bf16x2.f32 %0, %1, %2;" : "=r"(l) : "f"(l1), "f"(l0));
}

__device__ __forceinline__ void mma16816(float* d, const uint32_t* a, uint32_t b0, uint32_t b1) {
    asm volatile(
        "mma.sync.aligned.m16n8k16.row.col.f32.bf16.bf16.f32 "
        "{%0,%1,%2,%3}, {%4,%5,%6,%7}, {%8,%9}, {%0,%1,%2,%3};\n"
        : "+f"(d[0]), "+f"(d[1]), "+f"(d[2]), "+f"(d[3])
        : "r"(a[0]), "r"(a[1]), "r"(a[2]), "r"(a[3]), "r"(b0), "r"(b1));
}

#define CP_ASYNC16(smaddr, gptr) \
    asm volatile("cp.async.cg.shared.global [%0], [%1], 16;" :: "r"(smaddr), "l"(gptr) : "memory")
#define CP_COMMIT()  asm volatile("cp.async.commit_group;" ::: "memory")
#define CP_WAIT1()   asm volatile("cp.async.wait_group 1;" ::: "memory")
#define CP_WAIT0()   asm volatile("cp.async.wait_group 0;" ::: "memory")

// ---------------- prep: fp32 activations -> frag-ordered bf16 hi/lo ----------------
__global__ void prep_kernel(const float* __restrict__ x, const float* __restrict__ h) {
    int idx = blockIdx.x * blockDim.x + threadIdx.x;        // 0..65535
    int i2 = idx & 32767;
    const float* s = (idx < 32768) ? x : h;
    uint4* d = (idx < 32768) ? g_xfrag : g_hfrag;
    int t4 = i2 & 3, n = (i2 >> 2) & 31, c = i2 >> 7;
    int k0 = c * 16 + 2 * t4;
    float2 p0 = *(const float2*)&s[(size_t)n * H + k0];
    float2 p1 = *(const float2*)&s[(size_t)n * H + k0 + 8];
    uint4 v;
    split2(p0, v.x, v.z);
    split2(p1, v.y, v.w);
    d[i2] = v;
}

// ---------------- GEMM: gates = Wih@x^T + Whh@h^T + bih + bhh ----------------
// grid=128 CTAs, 256 threads. CTA owns 128 gate rows; warp w owns rows +w*16.
// K pipeline: 64 chunks (32 per weight matrix), cp.async double-buffered.
__global__ void __launch_bounds__(256, 1) gemm_kernel(
    const float* __restrict__ Wih, const float* __restrict__ Whh,
    const float* __restrict__ bih, const float* __restrict__ bhh)
{
    extern __shared__ char smem[];
    const int tid = threadIdx.x, lane = tid & 31, wid = tid >> 5;
    const int g = lane >> 2, t4 = lane & 3;
    const int m_base = blockIdx.x * 128;
    const int m0 = m_base + wid * 16;                 // warp's 16 rows
    const uint32_t sm0 = smem_u32(smem);

    float acc[4][4] = {};                             // 4 n-tiles x 4 f32

    // stage chunk ch (0..63) into buffer (ch&1)
    auto stage = [&](int ch) {
        const int pass = ch >> 5, cc = ch & 31;
        const float* W = pass ? Whh : Wih;
        const uint4* F = pass ? g_hfrag : g_xfrag;
        const uint32_t sb = sm0 + (uint32_t)(ch & 1) * STAGE;
        // A: 128 rows x 512B, as 4096 x 16B segments
        #pragma unroll
        for (int i = 0; i < 16; ++i) {
            int s = tid + i * 256;
            int row = s >> 5, seg = s & 31;
            const float* gp = W + (size_t)(m_base + row) * H + cc * 128 + seg * 4;
            const void* gg = (const void*)__cvta_generic_to_global((void*)gp);
            CP_ASYNC16(sb + (uint32_t)row * A_STRIDE_B + (uint32_t)seg * 16u, gg);
        }
        // B: 1024 x 16B frags
        #pragma unroll
        for (int i = 0; i < 4; ++i) {
            int s = tid + i * 256;
            const void* gg = (const void*)__cvta_generic_to_global((void*)(F + (size_t)cc * 1024 + s));
            CP_ASYNC16(sb + B_OFF + (uint32_t)s * 16u, gg);
        }
        CP_COMMIT();
    };

    stage(0);
    stage(1);

    #pragma unroll 1
    for (int ch = 0; ch < NCH; ++ch) {
        if (ch + 1 < NCH) { CP_WAIT1(); } else { CP_WAIT0(); }
        __syncthreads();

        const char* sb = smem + (ch & 1) * STAGE;
        const char* rowA0 = sb + (size_t)(wid * 16 + g) * A_STRIDE_B;        // row g
        const char* rowA1 = rowA0 + 8 * A_STRIDE_B;                          // row g+8
        const uint4* sB = (const uint4*)(sb + B_OFF);

        #pragma unroll
        for (int kk = 0; kk < CH; ++kk) {
            const int col = kk * 16 + 2 * t4;
            float2 a0 = *(const float2*)(rowA0 + col * 4);
            float2 a1 = *(const float2*)(rowA1 + col * 4);
            float2 a2 = *(const float2*)(rowA0 + (col + 8) * 4);
            float2 a3 = *(const float2*)(rowA1 + (col + 8) * 4);
            uint32_t ah[4], al[4];
            split2(a0, ah[0], al[0]);
            split2(a1, ah[1], al[1]);
            split2(a2, ah[2], al[2]);
            split2(a3, ah[3], al[3]);

            uint4 bb[4];
            #pragma unroll
            for (int t = 0; t < 4; ++t)
                bb[t] = sB[kk * 128 + (8 * t + g) * 4 + t4];   // {bh0,bh1,bl0,bl1}

            // term-outer order: consecutive MMAs hit independent acc[t] chains
            #pragma unroll
            for (int t = 0; t < 4; ++t) mma16816(acc[t], ah, bb[t].x, bb[t].y);  // Ah*Bh
            #pragma unroll
            for (int t = 0; t < 4; ++t) mma16816(acc[t], ah, bb[t].z, bb[t].w);  // Ah*Bl
            #pragma unroll
            for (int t = 0; t < 4; ++t) mma16816(acc[t], al, bb[t].x, bb[t].y);  // Al*Bh
        }
        __syncthreads();
        if (ch + 2 < NCH) stage(ch + 2);
    }

    // epilogue: add biases, write gates[j][b] (j-major, batch contiguous)
    const int j0 = m0 + g;
    const float bi0 = bih[j0] + bhh[j0];
    const float bi1 = bih[j0 + 8] + bhh[j0 + 8];
    #pragma unroll
    for (int t = 0; t < 4; ++t) {
        int colb = 8 * t + 2 * t4;
        *(float2*)&g_gates[(size_t)j0 * B + colb] =
            make_float2(acc[t][0] + bi0, acc[t][1] + bi0);
        *(float2*)&g_gates[(size_t)(j0 + 8) * B + colb] =
            make_float2(acc[t][2] + bi1, acc[t][3] + bi1);
    }
}

// ---------------- LSTM cell (elementwise) ----------------
__global__ void cell_kernel(const float* __restrict__ prev_c, float* __restrict__ out, int l) {
    int idx = blockIdx.x * blockDim.x + threadIdx.x;         // b*H + h
    int h = idx & (H - 1), b = idx >> 12;
    float gi = g_gates[(size_t)h * B + b];
    float gf = g_gates[(size_t)(H + h) * B + b];
    float gg = g_gates[(size_t)(2 * H + h) * B + b];
    float go = g_gates[(size_t)(3 * H + h) * B + b];
    float si = 1.f / (1.f + expf(-gi));
    float sf = 1.f / (1.f + expf(-gf));
    float so = 1.f / (1.f + expf(-go));
    float c = prev_c[(size_t)l * BH + idx];
    float cn = sf * c + si * tanhf(gg);
    float hn = so * tanhf(cn);
    out[(size_t)(0 * 2 + l) * BH + idx] = hn;                // next_h
    out[(size_t)(1 * 2 + l) * BH + idx] = cn;                // next_c
    if (l == 0) g_hnew[idx] = hn;                            // feeds layer 1
}

// ---------------- launch ----------------
extern "C" void kernel_launch(void* const* d_in, const int* in_sizes, int n_in,
                              void* d_out, int out_size) {
    const float* inputs = (const float*)d_in[0];
    const float* prev_h = (const float*)d_in[1];
    const float* prev_c = (const float*)d_in[2];
    const float* W_ih   = (const float*)d_in[3];
    const float* W_hh   = (const float*)d_in[4];
    const float* b_ih   = (const float*)d_in[5];
    const float* b_hh   = (const float*)d_in[6];
    float* out = (float*)d_out;

    static bool attr_set = false;
    if (!attr_set) {
        cudaFuncSetAttribute(gemm_kernel,
                             cudaFuncAttributeMaxDynamicSharedMemorySize, SMEM_TOTAL);
        attr_set = true;
    }

    float* hnew_ptr = nullptr;
    cudaGetSymbolAddress((void**)&hnew_ptr, g_hnew);

    // layer 0
    prep_kernel<<<256, 256>>>(inputs, prev_h);
    gemm_kernel<<<128, 256, SMEM_TOTAL>>>(W_ih, W_hh, b_ih, b_hh);
    cell_kernel<<<512, 256>>>(prev_c, out, 0);
    // layer 1
    prep_kernel<<<256, 256>>>(hnew_ptr, prev_h + (size_t)BH);
    gemm_kernel<<<128, 256, SMEM_TOTAL>>>(W_ih + (size_t)LAYER_W, W_hh + (size_t)LAYER_W,
                                          b_ih + (size_t)G4, b_hh + (size_t)G4);
    cell_kernel<<<512, 256>>>(prev_c, out, 1);
}